// round 1
// baseline (speedup 1.0000x reference)
#include <cuda_runtime.h>
#include <cuda_bf16.h>
#include <math.h>

#define N_NODES 100000
#define IN_DIM  128
#define HID     64
#define NCLS    40

// Scratch buffers (alloc-free rule: __device__ globals)
__device__ float g_A[(size_t)N_NODES * HID];   // support buffers
__device__ float g_B[(size_t)N_NODES * HID];   // aggregation buffers

// ---------------------------------------------------------------------------
// zero fill (float4)
// ---------------------------------------------------------------------------
__global__ void zero_kernel(float* __restrict__ p, int n4) {
    int i = blockIdx.x * blockDim.x + threadIdx.x;
    if (i < n4) reinterpret_cast<float4*>(p)[i] = make_float4(0.f, 0.f, 0.f, 0.f);
}

// ---------------------------------------------------------------------------
// Tiled GEMM: C[N,64] = act(X[N,K]) @ W[K,64] + b
// 64-node x 64-col tile, 256 threads, 4x4 per thread, K chunked by 32.
// ---------------------------------------------------------------------------
template<int K, bool RELU>
__global__ void gemm64_kernel(const float* __restrict__ X,
                              const float* __restrict__ W,
                              const float* __restrict__ b,
                              float* __restrict__ C, int N) {
    constexpr int BK = 32;
    __shared__ float Xs[64][BK];   // 8 KB
    __shared__ float Ws[BK][64];   // 8 KB

    const int tid = threadIdx.x;
    const int tx = tid & 15;       // column group: cols tx*4 .. tx*4+3
    const int ty = tid >> 4;       // node group:  nodes ty*4 .. ty*4+3
    const int nodeBase = blockIdx.x * 64;

    float acc[4][4];
    const float4 bv = *reinterpret_cast<const float4*>(b + tx * 4);
#pragma unroll
    for (int i = 0; i < 4; i++) {
        acc[i][0] = bv.x; acc[i][1] = bv.y; acc[i][2] = bv.z; acc[i][3] = bv.w;
    }

    for (int kc = 0; kc < K; kc += BK) {
        // Load X tile: 64 rows x 32 cols = 512 float4, 2 per thread.
#pragma unroll
        for (int t = 0; t < 2; t++) {
            int idx = tid + t * 256;          // 0..511
            int r   = idx >> 3;               // row 0..63
            int c4  = idx & 7;                // float4 col 0..7
            int node = nodeBase + r;
            float4 xv = make_float4(0.f, 0.f, 0.f, 0.f);
            if (node < N)
                xv = *reinterpret_cast<const float4*>(X + (size_t)node * K + kc + c4 * 4);
            if (RELU) {
                xv.x = fmaxf(xv.x, 0.f); xv.y = fmaxf(xv.y, 0.f);
                xv.z = fmaxf(xv.z, 0.f); xv.w = fmaxf(xv.w, 0.f);
            }
            *reinterpret_cast<float4*>(&Xs[r][c4 * 4]) = xv;
        }
        // Load W chunk: rows kc..kc+31 x 64 cols = contiguous 8 KB.
#pragma unroll
        for (int t = 0; t < 2; t++) {
            int idx = tid + t * 256;
            int r   = idx >> 4;               // 0..31
            int c4  = idx & 15;               // 0..15
            *reinterpret_cast<float4*>(&Ws[r][c4 * 4]) =
                *reinterpret_cast<const float4*>(W + (size_t)(kc + r) * 64 + c4 * 4);
        }
        __syncthreads();

#pragma unroll
        for (int kk = 0; kk < BK; kk++) {
            const float4 wv = *reinterpret_cast<const float4*>(&Ws[kk][tx * 4]);
            float xv[4];
#pragma unroll
            for (int i = 0; i < 4; i++) xv[i] = Xs[ty * 4 + i][kk];
#pragma unroll
            for (int i = 0; i < 4; i++) {
                acc[i][0] += xv[i] * wv.x;
                acc[i][1] += xv[i] * wv.y;
                acc[i][2] += xv[i] * wv.z;
                acc[i][3] += xv[i] * wv.w;
            }
        }
        __syncthreads();
    }

#pragma unroll
    for (int i = 0; i < 4; i++) {
        int node = nodeBase + ty * 4 + i;
        if (node < N) {
            float4 o = make_float4(acc[i][0], acc[i][1], acc[i][2], acc[i][3]);
            *reinterpret_cast<float4*>(C + (size_t)node * 64 + tx * 4) = o;
        }
    }
}

// ---------------------------------------------------------------------------
// SpMM: out[row[e], :] += val[e] * dense[col[e], :]   (64 cols)
// One warp processes 32 edges: coalesced metadata load, then per-edge
// broadcast; lane handles cols {lane, lane+32} -> unit-stride LDG + RED.
// ---------------------------------------------------------------------------
__global__ void spmm_kernel(const int* __restrict__ er, const int* __restrict__ ec,
                            const float* __restrict__ ev,
                            const float* __restrict__ D,
                            float* __restrict__ O, int E) {
    const int lane   = threadIdx.x & 31;
    const int warpId = (blockIdx.x * blockDim.x + threadIdx.x) >> 5;
    const int base   = warpId * 32;
    if (base >= E) return;

    int   r = 0, c = 0;
    float v = 0.f;
    const int e = base + lane;
    if (e < E) { r = er[e]; c = ec[e]; v = ev[e]; }
    const int cnt = min(32, E - base);

    for (int i = 0; i < cnt; i++) {
        const int   ri = __shfl_sync(0xffffffffu, r, i);
        const int   ci = __shfl_sync(0xffffffffu, c, i);
        const float vi = __shfl_sync(0xffffffffu, v, i);

        const float* src = D + (size_t)ci * 64;
        float*       dst = O + (size_t)ri * 64;
        const float a0 = src[lane];
        const float a1 = src[lane + 32];
        atomicAdd(dst + lane,      vi * a0);
        atomicAdd(dst + lane + 32, vi * a1);
    }
}

// ---------------------------------------------------------------------------
// Classifier: out = log_softmax(H @ Wc + bc), one warp per node.
// Lane computes classes {lane, lane+32(if lane<8)}; shuffle reductions.
// ---------------------------------------------------------------------------
__global__ void classifier_kernel(const float* __restrict__ H,
                                  const float* __restrict__ Wc,
                                  const float* __restrict__ bc,
                                  float* __restrict__ out, int N) {
    __shared__ float Ws[64 * 40 + 64];   // padded so the lane>=8 dummy column stays in-bounds
    __shared__ float bs[40];
    __shared__ float hs[8][64];

    const int tid  = threadIdx.x;
    const int lane = tid & 31;
    const int warp = tid >> 5;

    for (int i = tid; i < 64 * 40; i += 256) Ws[i] = Wc[i];
    for (int i = 64 * 40 + tid; i < 64 * 40 + 64; i += 256) Ws[i] = 0.f;
    if (tid < 40) bs[tid] = bc[tid];
    __syncthreads();

    for (int it = 0; it < 4; it++) {
        const int node = blockIdx.x * 32 + it * 8 + warp;
        if (node < N) {
            __syncwarp();
            hs[warp][lane]      = H[(size_t)node * 64 + lane];
            hs[warp][lane + 32] = H[(size_t)node * 64 + lane + 32];
            __syncwarp();

            float v0 = bs[lane];
            float v1 = (lane < 8) ? bs[32 + lane] : 0.f;
#pragma unroll
            for (int k = 0; k < 64; k++) {
                const float h = hs[warp][k];
                v0 += h * Ws[k * 40 + lane];
                v1 += h * Ws[k * 40 + 32 + lane];   // padded region for lane>=8 (discarded)
            }

            float m = (lane < 8) ? fmaxf(v0, v1) : v0;
#pragma unroll
            for (int off = 16; off; off >>= 1)
                m = fmaxf(m, __shfl_xor_sync(0xffffffffu, m, off));
            float s = expf(v0 - m) + ((lane < 8) ? expf(v1 - m) : 0.f);
#pragma unroll
            for (int off = 16; off; off >>= 1)
                s += __shfl_xor_sync(0xffffffffu, s, off);
            const float lse = m + logf(s);

            out[(size_t)node * 40 + lane] = v0 - lse;
            if (lane < 8)
                out[(size_t)node * 40 + 32 + lane] = v1 - lse;
        }
    }
}

// ---------------------------------------------------------------------------
// launch
// ---------------------------------------------------------------------------
extern "C" void kernel_launch(void* const* d_in, const int* in_sizes, int n_in,
                              void* d_out, int out_size) {
    const float* x  = (const float*)d_in[0];
    const int*   er = (const int*)  d_in[1];
    const int*   ec = (const int*)  d_in[2];
    const float* ev = (const float*)d_in[3];
    const float* W1 = (const float*)d_in[4];
    const float* b1 = (const float*)d_in[5];
    const float* W2 = (const float*)d_in[6];
    const float* b2 = (const float*)d_in[7];
    const float* Wc = (const float*)d_in[8];
    const float* bc = (const float*)d_in[9];
    float* out = (float*)d_out;

    const int N = in_sizes[0] / IN_DIM;   // 100000
    const int E = in_sizes[1];            // 1600000

    void* pA_ = nullptr; void* pB_ = nullptr;
    cudaGetSymbolAddress(&pA_, g_A);
    cudaGetSymbolAddress(&pB_, g_B);
    float* A = (float*)pA_;
    float* B = (float*)pB_;

    const int gemmBlocks  = (N + 63) / 64;
    const int zeroN4      = (N * HID) / 4;
    const int zeroBlocks  = (zeroN4 + 255) / 256;
    const int spmmWarps   = (E + 31) / 32;
    const int spmmBlocks  = (spmmWarps + 7) / 8;
    const int clsBlocks   = (N + 31) / 32;

    // Layer 1: support = x@W1+b1 ; h1 = spmm(support)  (relu fused into GEMM2 read)
    gemm64_kernel<IN_DIM, false><<<gemmBlocks, 256>>>(x, W1, b1, A, N);
    zero_kernel<<<zeroBlocks, 256>>>(B, zeroN4);
    spmm_kernel<<<spmmBlocks, 256>>>(er, ec, ev, A, B, E);

    // Layer 2: support2 = relu(h1)@W2+b2 ; h2 = spmm(support2)
    gemm64_kernel<HID, true><<<gemmBlocks, 256>>>(B, W2, b2, A, N);
    zero_kernel<<<zeroBlocks, 256>>>(B, zeroN4);
    spmm_kernel<<<spmmBlocks, 256>>>(er, ec, ev, A, B, E);

    // Classifier + log-softmax
    classifier_kernel<<<clsBlocks, 256>>>(B, Wc, bc, out, N);
}